// round 11
// baseline (speedup 1.0000x reference)
#include <cuda_runtime.h>
#include <cuda_bf16.h>

// PointMatcher: pred (N,20,2) f32, gt (M,20,2) f32.
// distances(i,j) = mean_p sqrt((pred[i,p]-gt[j,p])^2 summed over xy)
// out = [ matched_points (N*40) | confidence (N) | indices-as-float (N) ]
//
// R5/R8: pred rows in smem (regs 237 -> ~60, single co-resident wave),
//        packed f32x2 math over point-pairs (gt staged negated so dx = add.f32x2),
//        dual accumulators per pred row. (R8 = R5 resubmit; infra failure.)

#define P_PTS    20
#define NPAIR    10               // point pairs
#define ROW_F    40               // floats per row
#define TI       4                // preds per block
#define TILE_J   256              // gt rows per smem tile
#define NTHREADS 256

typedef unsigned long long u64;

__device__ __forceinline__ u64 pack2(float lo, float hi) {
    u64 r; asm("mov.b64 %0, {%1, %2};" : "=l"(r) : "f"(lo), "f"(hi)); return r;
}
__device__ __forceinline__ void unpack2(u64 v, float& lo, float& hi) {
    asm("mov.b64 {%0, %1}, %2;" : "=f"(lo), "=f"(hi) : "l"(v));
}
__device__ __forceinline__ u64 add2(u64 a, u64 b) {
    u64 r; asm("add.rn.f32x2 %0, %1, %2;" : "=l"(r) : "l"(a), "l"(b)); return r;
}
__device__ __forceinline__ u64 mul2(u64 a, u64 b) {
    u64 r; asm("mul.rn.f32x2 %0, %1, %2;" : "=l"(r) : "l"(a), "l"(b)); return r;
}
__device__ __forceinline__ u64 fma2(u64 a, u64 b, u64 c) {
    u64 r; asm("fma.rn.f32x2 %0, %1, %2, %3;" : "=l"(r) : "l"(a), "l"(b), "l"(c)); return r;
}
__device__ __forceinline__ float fsqrt_approx(float x) {
    float r; asm("sqrt.approx.f32 %0, %1;" : "=f"(r) : "f"(x)); return r;
}

__global__ __launch_bounds__(NTHREADS)
void PointMatcher_kernel(const float* __restrict__ pred,
                         const float* __restrict__ gt,
                         float* __restrict__ out,
                         int N, int M)
{
    // gt tile, transposed and NEGATED, packed as (val_p, val_{p+1}) f32x2
    __shared__ u64 tX[NPAIR][TILE_J];     // -x pairs
    __shared__ u64 tY[NPAIR][TILE_J];     // -y pairs
    __shared__ u64 pX[TI][NPAIR];         // pred x pairs
    __shared__ u64 pY[TI][NPAIR];         // pred y pairs
    __shared__ float red_m[TI][NTHREADS / 32];
    __shared__ int   red_i[TI][NTHREADS / 32];
    __shared__ float best_m[TI];
    __shared__ int   best_i[TI];

    const int tid  = threadIdx.x;
    const int lane = tid & 31;
    const int warp = tid >> 5;
    const int i0   = blockIdx.x * TI;

    // ---- stage TI pred rows into smem as packed pairs ----
    if (tid < TI * NPAIR) {
        int i = tid / NPAIR;
        int q = tid % NPAIR;
        int row = i0 + i;
        if (row >= N) row = N - 1;
        // float4 at pair q = (x_{2q}, y_{2q}, x_{2q+1}, y_{2q+1})
        float4 v = __ldg(reinterpret_cast<const float4*>(pred + (size_t)row * ROW_F) + q);
        pX[i][q] = pack2(v.x, v.z);
        pY[i][q] = pack2(v.y, v.w);
    }

    float s0[TI], s1[TI];
    float mn[TI];
    int   mi[TI];
    #pragma unroll
    for (int i = 0; i < TI; i++) { mn[i] = 3.4e38f; mi[i] = 0; }

    const int numTiles = (M + TILE_J - 1) / TILE_J;

    for (int t = 0; t < numTiles; t++) {
        const int jBase = t * TILE_J;
        __syncthreads();   // protect tile (and pred smem on first iter)

        // ---- stage gt tile: transpose to [pair][j], negate, pack f32x2 ----
        {
            const float4* g4 = reinterpret_cast<const float4*>(gt + (size_t)jBase * ROW_F);
            #pragma unroll
            for (int k = 0; k < (TILE_J * NPAIR) / NTHREADS; k++) {
                int lin4 = tid + k * NTHREADS;       // [0, TILE_J*10)
                int jl   = lin4 / NPAIR;
                int q    = lin4 % NPAIR;
                float4 v = make_float4(-1e30f, -1e30f, -1e30f, -1e30f);
                if (jBase + jl < M) v = __ldg(g4 + lin4);
                tX[q][jl] = pack2(-v.x, -v.z);
                tY[q][jl] = pack2(-v.y, -v.w);
            }
        }
        __syncthreads();

        // ---- compute: this thread owns gt row j = jBase + tid ----
        const int jg = jBase + tid;
        if (jg < M) {
            #pragma unroll
            for (int i = 0; i < TI; i++) { s0[i] = 0.0f; s1[i] = 0.0f; }

            #pragma unroll
            for (int q = 0; q < NPAIR; q++) {
                u64 gx = tX[q][tid];
                u64 gy = tY[q][tid];
                #pragma unroll
                for (int i = 0; i < TI; i++) {
                    u64 dx = add2(pX[i][q], gx);     // pred + (-gt)
                    u64 dy = add2(pY[i][q], gy);
                    u64 sq = mul2(dx, dx);
                    u64 d2 = fma2(dy, dy, sq);
                    float lo, hi;
                    unpack2(d2, lo, hi);
                    s0[i] += fsqrt_approx(lo);
                    s1[i] += fsqrt_approx(hi);
                }
            }
            #pragma unroll
            for (int i = 0; i < TI; i++) {
                float d = (s0[i] + s1[i]) * (1.0f / P_PTS);
                if (d < mn[i]) { mn[i] = d; mi[i] = jg; }
            }
        }
    }
    __syncthreads();

    // ---- reduction: warp-level min+argmin (tie -> lower index) ----
    #pragma unroll
    for (int i = 0; i < TI; i++) {
        float m = mn[i];
        int   j = mi[i];
        #pragma unroll
        for (int off = 16; off > 0; off >>= 1) {
            float m2 = __shfl_down_sync(0xFFFFFFFFu, m, off);
            int   j2 = __shfl_down_sync(0xFFFFFFFFu, j, off);
            if (m2 < m || (m2 == m && j2 < j)) { m = m2; j = j2; }
        }
        if (lane == 0) { red_m[i][warp] = m; red_i[i][warp] = j; }
    }
    __syncthreads();

    if (tid < TI) {
        float m = red_m[tid][0];
        int   j = red_i[tid][0];
        #pragma unroll
        for (int w = 1; w < NTHREADS / 32; w++) {
            float m2 = red_m[tid][w];
            int   j2 = red_i[tid][w];
            if (m2 < m || (m2 == m && j2 < j)) { m = m2; j = j2; }
        }
        best_m[tid] = m;
        best_i[tid] = j;
    }
    __syncthreads();

    // ---- write outputs ----
    if (tid < TI * ROW_F) {
        int i = tid / ROW_F;
        int c = tid % ROW_F;
        if (i0 + i < N)
            out[(size_t)(i0 + i) * ROW_F + c] = __ldg(gt + (size_t)best_i[i] * ROW_F + c);
    }
    if (tid < TI) {
        int row = i0 + tid;
        if (row < N) {
            float m    = best_m[tid];
            float conf = (m > 2.0f) ? 0.0f : __expf(-m);
            out[(size_t)N * ROW_F + row]     = conf;                 // confidence
            out[(size_t)N * ROW_F + N + row] = (float)best_i[tid];   // index as float
        }
    }
}

extern "C" void kernel_launch(void* const* d_in, const int* in_sizes, int n_in,
                              void* d_out, int out_size) {
    const float* pred = (const float*)d_in[0];
    const float* gt   = (const float*)d_in[1];
    float*       out  = (float*)d_out;

    const int N = in_sizes[0] / ROW_F;   // 1024
    const int M = in_sizes[1] / ROW_F;   // 2048

    const int blocks = (N + TI - 1) / TI;
    PointMatcher_kernel<<<blocks, NTHREADS>>>(pred, gt, out, N, M);
}

// round 12
// speedup vs baseline: 1.2874x; 1.2874x over previous
#include <cuda_runtime.h>
#include <cuda_bf16.h>

// PointMatcher: pred (N,20,2) f32, gt (M,20,2) f32.
// out = [ matched_points (N*40) | confidence (N) | indices-as-float (N) ]
//
// R12: split-M two-stage. Stage 1: grid (N/TI, SPLIT) partial min/argmin over
// M/SPLIT gt rows each (fixes grid-limited occupancy: 256 -> 1024 blocks).
// LDS.128 for both gt tile and pred (halves LDS instr count). f32x2 math,
// gt staged negated. Stage 2: reduce SPLIT partials, gather matched rows.

#define P_PTS    20
#define NPAIR    10
#define NQ2      5                // pair-of-pairs
#define ROW_F    40
#define TI       4                // preds per block
#define TILE_J   128              // gt rows per tile = NTHREADS
#define NTHREADS 128
#define SPLIT    4

typedef unsigned long long u64;

#define MAXN 4096
__device__ float g_pmin[MAXN * SPLIT];
__device__ int   g_pidx[MAXN * SPLIT];

__device__ __forceinline__ u64 pack2(float lo, float hi) {
    u64 r; asm("mov.b64 %0, {%1, %2};" : "=l"(r) : "f"(lo), "f"(hi)); return r;
}
__device__ __forceinline__ void unpack2(u64 v, float& lo, float& hi) {
    asm("mov.b64 {%0, %1}, %2;" : "=f"(lo), "=f"(hi) : "l"(v));
}
__device__ __forceinline__ u64 add2(u64 a, u64 b) {
    u64 r; asm("add.rn.f32x2 %0, %1, %2;" : "=l"(r) : "l"(a), "l"(b)); return r;
}
__device__ __forceinline__ u64 mul2(u64 a, u64 b) {
    u64 r; asm("mul.rn.f32x2 %0, %1, %2;" : "=l"(r) : "l"(a), "l"(b)); return r;
}
__device__ __forceinline__ u64 fma2(u64 a, u64 b, u64 c) {
    u64 r; asm("fma.rn.f32x2 %0, %1, %2, %3;" : "=l"(r) : "l"(a), "l"(b), "l"(c)); return r;
}
__device__ __forceinline__ float fsqrt_approx(float x) {
    float r; asm("sqrt.approx.f32 %0, %1;" : "=f"(r) : "f"(x)); return r;
}

// ---------------- Stage 1: partial min/argmin ----------------
__global__ __launch_bounds__(NTHREADS)
void PointMatcher_stage1(const float* __restrict__ pred,
                         const float* __restrict__ gt,
                         int N, int M)
{
    // gt tile, transposed, NEGATED, pairs-of-pairs for LDS.128:
    // tX[q2][j][0..1] = x-pairs for points {4q2,4q2+1} and {4q2+2,4q2+3}... no:
    // q2 groups point-pairs q=2*q2 and q=2*q2+1. [j][2] contiguous -> 16B.
    __shared__ u64 tX[NQ2][TILE_J][2];
    __shared__ u64 tY[NQ2][TILE_J][2];
    __shared__ u64 pX[TI][NPAIR];     // [i][q], 16B-aligned pairs at even q
    __shared__ u64 pY[TI][NPAIR];
    __shared__ float red_m[TI][NTHREADS / 32];
    __shared__ int   red_i[TI][NTHREADS / 32];

    const int tid   = threadIdx.x;
    const int lane  = tid & 31;
    const int warp  = tid >> 5;
    const int i0    = blockIdx.x * TI;
    const int split = blockIdx.y;

    const int chunk  = (M + SPLIT - 1) / SPLIT;
    const int jStart = split * chunk;
    const int jEnd   = min(jStart + chunk, M);

    // ---- stage TI pred rows into smem as packed pairs ----
    if (tid < TI * NPAIR) {
        int i = tid / NPAIR;
        int q = tid % NPAIR;
        int row = i0 + i;
        if (row >= N) row = N - 1;
        float4 v = __ldg(reinterpret_cast<const float4*>(pred + (size_t)row * ROW_F) + q);
        pX[i][q] = pack2(v.x, v.z);
        pY[i][q] = pack2(v.y, v.w);
    }

    float mn[TI];
    int   mi[TI];
    #pragma unroll
    for (int i = 0; i < TI; i++) { mn[i] = 3.4e38f; mi[i] = jStart; }

    for (int jBase = jStart; jBase < jEnd; jBase += TILE_J) {
        __syncthreads();

        // ---- stage gt tile: [q2][j][q&1], negated, packed ----
        {
            const float4* g4 = reinterpret_cast<const float4*>(gt + (size_t)jBase * ROW_F);
            #pragma unroll
            for (int k = 0; k < (TILE_J * NPAIR) / NTHREADS; k++) {
                int lin4 = tid + k * NTHREADS;       // [0, TILE_J*10)
                int jl   = lin4 / NPAIR;
                int q    = lin4 % NPAIR;
                float4 v = make_float4(-1e30f, -1e30f, -1e30f, -1e30f);
                if (jBase + jl < M) v = __ldg(g4 + lin4);
                tX[q >> 1][jl][q & 1] = pack2(-v.x, -v.z);
                tY[q >> 1][jl][q & 1] = pack2(-v.y, -v.w);
            }
        }
        __syncthreads();

        const int jg = jBase + tid;
        if (jg < jEnd) {
            float s0[TI], s1[TI];
            #pragma unroll
            for (int i = 0; i < TI; i++) { s0[i] = 0.0f; s1[i] = 0.0f; }

            #pragma unroll
            for (int q2 = 0; q2 < NQ2; q2++) {
                // LDS.128: two x-pairs and two y-pairs of this gt row
                ulonglong2 gx = *reinterpret_cast<const ulonglong2*>(&tX[q2][tid][0]);
                ulonglong2 gy = *reinterpret_cast<const ulonglong2*>(&tY[q2][tid][0]);
                #pragma unroll
                for (int i = 0; i < TI; i++) {
                    // LDS.128 broadcast: pred pairs 2q2, 2q2+1
                    ulonglong2 px = *reinterpret_cast<const ulonglong2*>(&pX[i][2 * q2]);
                    ulonglong2 py = *reinterpret_cast<const ulonglong2*>(&pY[i][2 * q2]);
                    u64 dxa = add2(px.x, gx.x);
                    u64 dya = add2(py.x, gy.x);
                    u64 dxb = add2(px.y, gx.y);
                    u64 dyb = add2(py.y, gy.y);
                    u64 d2a = fma2(dya, dya, mul2(dxa, dxa));
                    u64 d2b = fma2(dyb, dyb, mul2(dxb, dxb));
                    float a0, a1, b0, b1;
                    unpack2(d2a, a0, a1);
                    unpack2(d2b, b0, b1);
                    s0[i] += fsqrt_approx(a0) + fsqrt_approx(b0);
                    s1[i] += fsqrt_approx(a1) + fsqrt_approx(b1);
                }
            }
            #pragma unroll
            for (int i = 0; i < TI; i++) {
                float d = (s0[i] + s1[i]) * (1.0f / P_PTS);
                if (d < mn[i]) { mn[i] = d; mi[i] = jg; }
            }
        }
    }
    __syncthreads();

    // ---- block reduction: min+argmin (tie -> lower index) ----
    #pragma unroll
    for (int i = 0; i < TI; i++) {
        float m = mn[i];
        int   j = mi[i];
        #pragma unroll
        for (int off = 16; off > 0; off >>= 1) {
            float m2 = __shfl_down_sync(0xFFFFFFFFu, m, off);
            int   j2 = __shfl_down_sync(0xFFFFFFFFu, j, off);
            if (m2 < m || (m2 == m && j2 < j)) { m = m2; j = j2; }
        }
        if (lane == 0) { red_m[i][warp] = m; red_i[i][warp] = j; }
    }
    __syncthreads();

    if (tid < TI) {
        float m = red_m[tid][0];
        int   j = red_i[tid][0];
        #pragma unroll
        for (int w = 1; w < NTHREADS / 32; w++) {
            float m2 = red_m[tid][w];
            int   j2 = red_i[tid][w];
            if (m2 < m || (m2 == m && j2 < j)) { m = m2; j = j2; }
        }
        int row = i0 + tid;
        if (row < N) {
            g_pmin[(size_t)row * SPLIT + split] = m;
            g_pidx[(size_t)row * SPLIT + split] = j;
        }
    }
}

// ---------------- Stage 2: reduce partials, gather, outputs ----------------
__global__ __launch_bounds__(256)
void PointMatcher_stage2(const float* __restrict__ gt,
                         float* __restrict__ out,
                         int N, int M)
{
    int row = blockIdx.x * blockDim.x + threadIdx.x;
    if (row >= N) return;

    // splits cover increasing j ranges; strict < keeps lowest j on ties
    float m = g_pmin[(size_t)row * SPLIT + 0];
    int   j = g_pidx[(size_t)row * SPLIT + 0];
    #pragma unroll
    for (int s = 1; s < SPLIT; s++) {
        float m2 = g_pmin[(size_t)row * SPLIT + s];
        int   j2 = g_pidx[(size_t)row * SPLIT + s];
        if (m2 < m) { m = m2; j = j2; }
    }

    // gather matched gt row (40 floats = 10 float4)
    const float4* src = reinterpret_cast<const float4*>(gt + (size_t)j * ROW_F);
    float4*       dst = reinterpret_cast<float4*>(out + (size_t)row * ROW_F);
    #pragma unroll
    for (int k = 0; k < ROW_F / 4; k++) dst[k] = __ldg(src + k);

    float conf = (m > 2.0f) ? 0.0f : __expf(-m);
    out[(size_t)N * ROW_F + row]     = conf;          // confidence
    out[(size_t)N * ROW_F + N + row] = (float)j;      // index as float
}

extern "C" void kernel_launch(void* const* d_in, const int* in_sizes, int n_in,
                              void* d_out, int out_size) {
    const float* pred = (const float*)d_in[0];
    const float* gt   = (const float*)d_in[1];
    float*       out  = (float*)d_out;

    const int N = in_sizes[0] / ROW_F;   // 1024
    const int M = in_sizes[1] / ROW_F;   // 2048

    dim3 grid1((N + TI - 1) / TI, SPLIT);
    PointMatcher_stage1<<<grid1, NTHREADS>>>(pred, gt, N, M);

    const int blocks2 = (N + 255) / 256;
    PointMatcher_stage2<<<blocks2, 256>>>(gt, out, N, M);
}